// round 15
// baseline (speedup 1.0000x reference)
#include <cuda_runtime.h>
#include <cuda_bf16.h>
#include <cstdint>

#define NB  4
#define NTQ 512
#define NTK 512
#define NE  128
#define NF  256   // TWO_E
#define NT2 256   // NTK/2 (t-pairs)

// Scratch (no allocations allowed)
__device__ float    g_qproj[NB * NTQ * NE];                 // 1 MB
__device__ float    g_kproj[NB * NTK * NE];                 // 1 MB
__device__ float    g_zr[NB * NTK];                         // 1/rowsum per (b,t)
__device__ uint32_t g_ph[(size_t)NB * NT2 * NTQ];           // 2 MB  p hi, bf16 t-pairs [t2][q]
__device__ uint32_t g_pl[(size_t)NB * NT2 * NTQ];           // 2 MB  p lo
__device__ uint32_t g_vh[(size_t)NB * NT2 * NF];            // 1 MB  value*zr hi, [t2][d] (t2-major!)
__device__ uint32_t g_vl[(size_t)NB * NT2 * NF];            // 1 MB  value*zr lo

__device__ __forceinline__ float tanh_fast(float x) {
    float y;
    asm("tanh.approx.f32 %0, %1;" : "=f"(y) : "f"(x));
    return y;
}

// ---- packed fp32x2 helpers ----
__device__ __forceinline__ unsigned long long pack2(float x, float y) {
    unsigned long long r;
    asm("mov.b64 %0, {%1, %2};" : "=l"(r) : "f"(x), "f"(y));
    return r;
}
__device__ __forceinline__ void ffma2(unsigned long long& d,
                                      unsigned long long a, unsigned long long b) {
    asm("fma.rn.f32x2 %0, %1, %2, %0;" : "+l"(d) : "l"(a), "l"(b));
}
__device__ __forceinline__ float2 unpack2(unsigned long long v) {
    float2 f;
    asm("mov.b64 {%0, %1}, %2;" : "=f"(f.x), "=f"(f.y) : "l"(v));
    return f;
}

// ---- cp.async helpers ----
__device__ __forceinline__ uint32_t smem_u32(const void* p) {
    return (uint32_t)__cvta_generic_to_shared(p);
}
__device__ __forceinline__ void cp16(uint32_t dst, const void* src) {
    asm volatile("cp.async.ca.shared.global [%0], [%1], 16;"
                 :: "r"(dst), "l"(src) : "memory");
}
__device__ __forceinline__ void cp_commit() {
    asm volatile("cp.async.commit_group;" ::: "memory");
}
template <int N>
__device__ __forceinline__ void cp_wait() {
    asm volatile("cp.async.wait_group %0;" :: "n"(N) : "memory");
}

// ---- bf16 split helpers ----
__device__ __forceinline__ void bf16_split(float x, uint16_t& hi, uint16_t& lo) {
    __nv_bfloat16 h = __float2bfloat16(x);
    float r = x - __bfloat162float(h);
    __nv_bfloat16 l = __float2bfloat16(r);
    hi = __bfloat16_as_ushort(h);
    lo = __bfloat16_as_ushort(l);
}

// ---- mma.sync m16n8k16 bf16 (fp32 accum) ----
__device__ __forceinline__ void mma_bf16(float* c, const uint32_t* a,
                                         uint32_t b0, uint32_t b1) {
    asm volatile(
        "mma.sync.aligned.m16n8k16.row.col.f32.bf16.bf16.f32 "
        "{%0,%1,%2,%3}, {%4,%5,%6,%7}, {%8,%9}, {%0,%1,%2,%3};"
        : "+f"(c[0]), "+f"(c[1]), "+f"(c[2]), "+f"(c[3])
        : "r"(a[0]), "r"(a[1]), "r"(a[2]), "r"(a[3]), "r"(b0), "r"(b1));
}

// ---------------------------------------------------------------------------
// Kernel A: projections (unchanged from R10/R11 best).
// ---------------------------------------------------------------------------
__global__ __launch_bounds__(256) void proj_kernel(
    const float* __restrict__ query, const float* __restrict__ key,
    const float* __restrict__ W1, const float* __restrict__ W2)
{
    const float* A; const float* W; float* C;
    if (blockIdx.y == 0) { A = query; W = W1; C = g_qproj; }
    else                 { A = key;   W = W2; C = g_kproj; }

    __shared__ float As[2][32][32];
    __shared__ float Bs[2][32][128];

    const int tid = threadIdx.x;
    const int tx = tid & 31;
    const int ty = tid >> 5;
    const int row0 = blockIdx.x * 32;

    const int a_r  = tid >> 3;
    const int a_c  = (tid & 7) << 2;
    const float* a_src = A + (size_t)(row0 + a_r) * NF + a_c;

    auto issue_stage = [&](int st) {
        const int buf = st & 1;
        const int kk  = st << 5;
        cp16(smem_u32(&As[buf][a_r][a_c]), a_src + kk);
        #pragma unroll
        for (int i = 0; i < 4; i++) {
            int c  = tid + (i << 8);
            int k  = c >> 5;
            int n4 = (c & 31) << 2;
            cp16(smem_u32(&Bs[buf][k][n4]), W + (size_t)(kk + k) * NE + n4);
        }
        cp_commit();
    };

    issue_stage(0);

    unsigned long long acc2[4][2];
    #pragma unroll
    for (int i = 0; i < 4; i++) { acc2[i][0] = 0ULL; acc2[i][1] = 0ULL; }

    #pragma unroll
    for (int it = 0; it < 8; it++) {
        const int buf = it & 1;
        cp_wait<0>();
        __syncthreads();
        if (it < 7) issue_stage(it + 1);

        #pragma unroll
        for (int k4 = 0; k4 < 32; k4 += 4) {
            float a[4][4];
            #pragma unroll
            for (int i = 0; i < 4; i++) {
                float4 av = *(const float4*)&As[buf][(ty << 2) + i][k4];
                a[i][0] = av.x; a[i][1] = av.y; a[i][2] = av.z; a[i][3] = av.w;
            }
            #pragma unroll
            for (int j = 0; j < 4; j++) {
                ulonglong2 bp = *(const ulonglong2*)&Bs[buf][k4 + j][tx << 2];
                #pragma unroll
                for (int i = 0; i < 4; i++) {
                    unsigned long long aa = pack2(a[i][j], a[i][j]);
                    ffma2(acc2[i][0], aa, bp.x);
                    ffma2(acc2[i][1], aa, bp.y);
                }
            }
        }
    }

    #pragma unroll
    for (int i = 0; i < 4; i++) {
        float2 f01 = unpack2(acc2[i][0]);
        float2 f23 = unpack2(acc2[i][1]);
        float4 v = make_float4(f01.x, f01.y, f23.x, f23.y);
        *(float4*)(C + (size_t)(row0 + (ty << 2) + i) * NE + (tx << 2)) = v;
    }
}

// ---------------------------------------------------------------------------
// Kernel B: scores + exp + row-reciprocal (R11/R13 f32-tanh form, unchanged).
// Emits p as packed bf16 t-pairs (hi/lo) for the mma out kernel.
// ---------------------------------------------------------------------------
__global__ __launch_bounds__(256) void score_kernel(const float* __restrict__ vc)
{
    __shared__ float ks[8][128];
    __shared__ float qs[2][32][129];
    __shared__ float vcs[128];
    __shared__ float pex[8][32];       // per-chunk p exchange for t-pairing

    const int b   = blockIdx.y;
    const int t0  = blockIdx.x << 3;
    const int tid = threadIdx.x;
    const int w    = tid >> 5;
    const int lane = tid & 31;

    {   // k tile [8 x 128]
        int lin = tid << 2;
        int r = lin >> 7, c = lin & 127;
        *(float4*)&ks[r][c] =
            *(const float4*)(g_kproj + (size_t)(b * NTK + t0 + r) * NE + c);
    }
    if (tid < 128) vcs[tid] = vc[tid];

    const int c0    = tid & 127;
    const int rbase = tid >> 7;
    const float* qbase = g_qproj + (size_t)b * NTQ * NE + rbase * NE + c0;

    float pref[16];
    #pragma unroll
    for (int i = 0; i < 16; i++)
        pref[i] = qbase[(size_t)(2 * i) * NE];
    #pragma unroll
    for (int i = 0; i < 16; i++)
        qs[0][rbase + 2 * i][c0] = pref[i];
    __syncthreads();

    const int t = t0 + w;
    float zsum = 0.f;
    uint32_t* __restrict__ phrow = g_ph + ((size_t)b * NT2 + (t0 >> 1) + w) * NTQ;
    uint32_t* __restrict__ plrow = g_pl + ((size_t)b * NT2 + (t0 >> 1) + w) * NTQ;

    for (int ch = 0; ch < 16; ch++) {
        const int buf = ch & 1;
        if (ch < 15) {
            const float* src = qbase + (size_t)(ch + 1) * 32 * NE;
            #pragma unroll
            for (int i = 0; i < 16; i++)
                pref[i] = src[(size_t)(2 * i) * NE];
        }

        const float* __restrict__ kr = ks[w];
        const float* __restrict__ q0 = qs[buf][lane];
        float acc0 = 0.f;
        #pragma unroll 16
        for (int e = 0; e < 128; e++)
            acc0 += vcs[e] * tanh_fast(kr[e] + q0[e]);

        float p0 = __expf(acc0);
        pex[w][lane] = p0;
        zsum += p0;

        __syncthreads();               // pex visible; qs[buf] reads done
        if (w < 4) {                   // warps 0-3 emit packed t-pairs
            float pe = pex[2 * w][lane];
            float po = pex[2 * w + 1][lane];
            uint16_t he, le, ho, lo;
            bf16_split(pe, he, le);
            bf16_split(po, ho, lo);
            phrow[ch * 32 + lane] = ((uint32_t)ho << 16) | he;
            plrow[ch * 32 + lane] = ((uint32_t)lo << 16) | le;
        }
        if (ch < 15) {
            #pragma unroll
            for (int i = 0; i < 16; i++)
                qs[buf ^ 1][rbase + 2 * i][c0] = pref[i];
        }
        __syncthreads();               // qs refilled; pex consumed before rewrite
    }

    #pragma unroll
    for (int off = 16; off; off >>= 1)
        zsum += __shfl_xor_sync(0xffffffffu, zsum, off);
    if (lane == 0) g_zr[b * NTK + t] = 1.0f / zsum;
}

// ---------------------------------------------------------------------------
// Kernel B2: value*zr -> packed bf16 t-pairs, TRANSPOSED to [t2][d] order.
// Block: 32 d x 32 t2 tile, 256 threads, smem transpose (both sides coalesced).
// ---------------------------------------------------------------------------
__global__ __launch_bounds__(256) void conv_kernel(const float* __restrict__ value)
{
    __shared__ uint32_t sh[32][33];    // [t2local][dlocal] hi
    __shared__ uint32_t sl[32][33];
    __shared__ float   zrs[64];

    const int b   = blockIdx.z;
    const int d0  = blockIdx.x << 5;
    const int t20 = blockIdx.y << 5;
    const int tid = threadIdx.x;

    if (tid < 64) zrs[tid] = g_zr[b * NTK + 2 * t20 + tid];

    const int row   = tid >> 3;            // d local 0..31
    const int col16 = (tid & 7) << 3;      // t float offset 0..56
    const float* src = value + (size_t)(b * NF + d0 + row) * NTK + 2 * t20 + col16;
    float4 v0 = *(const float4*)(src);
    float4 v1 = *(const float4*)(src + 4);
    float vv[8] = {v0.x, v0.y, v0.z, v0.w, v1.x, v1.y, v1.z, v1.w};

    __syncthreads();                       // zrs ready

    #pragma unroll
    for (int j = 0; j < 4; j++) {
        float e = vv[2 * j]     * zrs[col16 + 2 * j];
        float o = vv[2 * j + 1] * zrs[col16 + 2 * j + 1];
        uint16_t he, le, ho, lo;
        bf16_split(e, he, le);
        bf16_split(o, ho, lo);
        int t2l = (col16 >> 1) + j;
        sh[t2l][row] = ((uint32_t)ho << 16) | he;
        sl[t2l][row] = ((uint32_t)lo << 16) | le;
    }
    __syncthreads();

    const int tr = tid >> 3;               // t2 local
    const int tc = (tid & 7) << 2;         // d local chunk
    uint4 wh = make_uint4(sh[tr][tc], sh[tr][tc + 1], sh[tr][tc + 2], sh[tr][tc + 3]);
    uint4 wl = make_uint4(sl[tr][tc], sl[tr][tc + 1], sl[tr][tc + 2], sl[tr][tc + 3]);
    size_t dst = (size_t)(b * NT2 + t20 + tr) * NF + d0 + tc;
    *(uint4*)(g_vh + dst) = wh;
    *(uint4*)(g_vl + dst) = wl;
}

// ---------------------------------------------------------------------------
// Kernel C: out via mma.sync bf16 3-term split.
// 4-stage cp.async pipeline, stage = 8 t2 (16 t), 32 iters, graded waits.
// A stored t2-major [8 t2][64 d] stride 72 — same conflict-free pattern as B.
// 512 threads, 16 warps 4m x 4n, warp tile 16x16.  smem 4*9KB = 36KB.
// ---------------------------------------------------------------------------
__global__ __launch_bounds__(512) void out_kernel(float* __restrict__ out)
{
    __shared__ uint32_t Ah[4][8][72];    // [buf][t2][d], data cols 0..63
    __shared__ uint32_t Al[4][8][72];
    __shared__ uint32_t Bh[4][8][72];    // [buf][t2][q], data cols 0..63
    __shared__ uint32_t Bl[4][8][72];

    const int b  = blockIdx.z;
    const int n0 = blockIdx.x << 6;
    const int m0 = blockIdx.y << 6;
    const int tid = threadIdx.x;
    const int w    = tid >> 5;
    const int lane = tid & 31;
    const int wm   = w >> 2;             // 0-3
    const int wn   = w & 3;              // 0-3
    const int grp  = lane >> 2;          // 0-7
    const int tig  = lane & 3;           // 0-3

    const uint32_t* vhp = g_vh + (size_t)b * NT2 * NF + m0;   // [t2][d]
    const uint32_t* vlp = g_vl + (size_t)b * NT2 * NF + m0;
    const uint32_t* php = g_ph + (size_t)b * NT2 * NTQ + n0;  // [t2][q]
    const uint32_t* plp = g_pl + (size_t)b * NT2 * NTQ + n0;

    // cp.async: 512 chunks/stage, 1/thread.
    const int hsel = tid >> 8;                   // 0 -> hi, 1 -> lo
    const int t8   = tid & 255;
    const int isA  = (t8 < 128);
    const int ar   = (t8 & 127) >> 4;            // row (t2) 0..7
    const int ac   = (t8 & 15) << 2;             // col chunk

    auto issue_stage = [&](int st) {
        const int bufi = st & 3;
        const int kk2  = st << 3;                // t2 offset
        if (isA) {
            const uint32_t* srcp = (hsel == 0) ? vhp : vlp;
            uint32_t dst = (hsel == 0) ? smem_u32(&Ah[bufi][ar][ac])
                                       : smem_u32(&Al[bufi][ar][ac]);
            cp16(dst, srcp + (size_t)(kk2 + ar) * NF + ac);
        } else {
            const uint32_t* srcp = (hsel == 0) ? php : plp;
            uint32_t dst = (hsel == 0) ? smem_u32(&Bh[bufi][ar][ac])
                                       : smem_u32(&Bl[bufi][ar][ac]);
            cp16(dst, srcp + (size_t)(kk2 + ar) * NTQ + ac);
        }
        cp_commit();
    };

    issue_stage(0);
    issue_stage(1);
    issue_stage(2);

    float acc[2][4];                     // [nf][reg]
    #pragma unroll
    for (int j = 0; j < 2; j++)
        #pragma unroll
        for (int r = 0; r < 4; r++) acc[j][r] = 0.f;

    #pragma unroll
    for (int it = 0; it < 32; it++) {
        const int bufi = it & 3;
        if (it < 30)      cp_wait<2>();
        else if (it == 30) cp_wait<1>();
        else               cp_wait<0>();
        __syncthreads();
        if (it < 29) issue_stage(it + 3);

        uint32_t ah[4], al[4];
        {
            const int mb = wm * 16;
            ah[0] = Ah[bufi][tig    ][mb + grp];
            ah[1] = Ah[bufi][tig    ][mb + grp + 8];
            ah[2] = Ah[bufi][tig + 4][mb + grp];
            ah[3] = Ah[bufi][tig + 4][mb + grp + 8];
            al[0] = Al[bufi][tig    ][mb + grp];
            al[1] = Al[bufi][tig    ][mb + grp + 8];
            al[2] = Al[bufi][tig + 4][mb + grp];
            al[3] = Al[bufi][tig + 4][mb + grp + 8];
        }
        #pragma unroll
        for (int nf = 0; nf < 2; nf++) {
            const int nb = wn * 16 + nf * 8 + grp;
            uint32_t bh0 = Bh[bufi][tig    ][nb];
            uint32_t bh1 = Bh[bufi][tig + 4][nb];
            uint32_t bl0 = Bl[bufi][tig    ][nb];
            uint32_t bl1 = Bl[bufi][tig + 4][nb];
            mma_bf16(acc[nf], ah, bh0, bh1);
            mma_bf16(acc[nf], ah, bl0, bl1);
            mma_bf16(acc[nf], al, bh0, bh1);
        }
    }

    // epilogue
    #pragma unroll
    for (int nf = 0; nf < 2; nf++) {
        const int row = m0 + wm * 16 + grp;
        const int col = n0 + wn * 16 + nf * 8 + tig * 2;
        float* dst0 = out + (size_t)(b * NF + row) * NTQ + col;
        float* dst1 = dst0 + 8 * NTQ;
        *(float2*)dst0 = make_float2(acc[nf][0], acc[nf][1]);
        *(float2*)dst1 = make_float2(acc[nf][2], acc[nf][3]);
    }
}

// ---------------------------------------------------------------------------
extern "C" void kernel_launch(void* const* d_in, const int* in_sizes, int n_in,
                              void* d_out, int out_size)
{
    const float* query = (const float*)d_in[0];
    const float* key   = (const float*)d_in[1];
    const float* value = (const float*)d_in[2];
    const float* W1    = (const float*)d_in[3];
    const float* W2    = (const float*)d_in[4];
    const float* vc    = (const float*)d_in[5];
    float* out = (float*)d_out;

    proj_kernel <<<dim3(64, 2), 256>>>(query, key, W1, W2);
    score_kernel<<<dim3(64, 4), 256>>>(vc);
    conv_kernel <<<dim3(8, 8, 4), 256>>>(value);
    out_kernel  <<<dim3(8, 4, 4), 512>>>(out);
}